// round 13
// baseline (speedup 1.0000x reference)
#include <cuda_runtime.h>
#include <cuda_bf16.h>
#include <cuda_fp16.h>
#include <cstdint>

// Problem constants (DRewGIN: N=50000 nodes, E=800000 edges, D=128, L=3)
#define NMAX 50000
#define EMAX 800000
#define DIM  128
#define LAY  3
#define APITCH 136   // smem row pitch in bf16 elements (272 B -> conflict-free frag loads)

// ---------------- device scratch (static, no allocation) ----------------
__device__ float g_x1[NMAX * DIM];
__device__ float g_x2[NMAX * DIM];
__device__ __half g_sout[NMAX * DIM];   // fp16: halves gather-side L2 traffic
__device__ __half g_z0[NMAX * DIM];
__device__ __half g_z1[NMAX * DIM];
__device__ __half g_z2[NMAX * DIM];
__device__ __nv_bfloat16 g_whT[12 * DIM * DIM];  // weight^T hi planes [n][k]
__device__ __nv_bfloat16 g_wlT[12 * DIM * DIM];  // weight^T lo planes [n][k]
__device__ int g_count[NMAX + 64];
__device__ int g_rowptr[NMAX + 1];
__device__ int g_wptr[NMAX];
__device__ int g_bsum[64];
__device__ int g_boff[64];
__device__ unsigned g_edges[EMAX];   // packed: src (16b) | attr<<16

// ---------------- CSR build ----------------
__global__ void zero_count_k(int n) {
    int i = blockIdx.x * blockDim.x + threadIdx.x;
    if (i < n) g_count[i] = 0;
}
__global__ void count_k(const int* __restrict__ dst, int e) {
    int i = blockIdx.x * blockDim.x + threadIdx.x;
    if (i < e) atomicAdd(&g_count[dst[i]], 1);
}

__global__ void scan1_k(int n) {
    __shared__ int wsum[8];
    const int tid = threadIdx.x;               // 256 threads
    const int base = blockIdx.x * 1024 + tid * 4;
    int4 c = make_int4(0, 0, 0, 0);
    if (base < n) c = *(const int4*)&g_count[base];
    int s0 = c.x;
    int s1 = s0 + c.y;
    int s2 = s1 + c.z;
    int s3 = s2 + c.w;
    int lane = tid & 31, wid = tid >> 5;
    int v = s3;
#pragma unroll
    for (int off = 1; off < 32; off <<= 1) {
        int u = __shfl_up_sync(0xffffffffu, v, off);
        if (lane >= off) v += u;
    }
    if (lane == 31) wsum[wid] = v;
    __syncthreads();
    if (wid == 0) {
        int w = (lane < 8) ? wsum[lane] : 0;
#pragma unroll
        for (int off = 1; off < 8; off <<= 1) {
            int u = __shfl_up_sync(0xffffffffu, w, off);
            if (lane >= off) w += u;
        }
        if (lane < 8) wsum[lane] = w;
        if (lane == 7) g_bsum[blockIdx.x] = w;
    }
    __syncthreads();
    int excl = v - s3 + (wid ? wsum[wid - 1] : 0);
    if (base < n) {
        g_rowptr[base + 0] = excl;
        g_rowptr[base + 1] = excl + s0;
        g_rowptr[base + 2] = excl + s1;
        g_rowptr[base + 3] = excl + s2;
    }
}
__global__ void scan2_k(int nb) {
    int tid = threadIdx.x;   // 64
    int v = (tid < nb) ? g_bsum[tid] : 0;
    __shared__ int sh[64];
    sh[tid] = v;
    __syncthreads();
    for (int off = 1; off < 64; off <<= 1) {
        int u = (tid >= off) ? sh[tid - off] : 0;
        __syncthreads();
        sh[tid] += u;
        __syncthreads();
    }
    if (tid < nb) g_boff[tid] = sh[tid] - v;
}
__global__ void scan3_k(int n, int e) {
    int i = blockIdx.x * blockDim.x + threadIdx.x;
    if (i < n) {
        int r = g_rowptr[i] + g_boff[i >> 10];
        g_rowptr[i] = r;
        g_wptr[i] = r;
    }
    if (i == 0) g_rowptr[n] = e;
}

__global__ void place_k(const int* __restrict__ src, const int* __restrict__ dst,
                        const int* __restrict__ attr, int e) {
    int i = blockIdx.x * blockDim.x + threadIdx.x;
    if (i < e) {
        int pos = atomicAdd(&g_wptr[dst[i]], 1);
        g_edges[pos] = (unsigned)src[i] | ((unsigned)attr[i] << 16);
    }
}

// ---------------- weight preprocessing: transpose + bf16 split ----------------
__global__ void convw_k(const float* __restrict__ Ws, const float* __restrict__ Wk) {
    int slot = blockIdx.x;
    const float* W = (slot < 3) ? (Ws + (size_t)slot * DIM * DIM)
                                : (Wk + (size_t)(slot - 3) * DIM * DIM);
    __nv_bfloat16* oh = g_whT + (size_t)slot * DIM * DIM;
    __nv_bfloat16* ol = g_wlT + (size_t)slot * DIM * DIM;
    for (int i = threadIdx.x; i < DIM * DIM; i += blockDim.x) {
        int nn = i >> 7, kk = i & 127;
        float w = W[kk * DIM + nn];
        __nv_bfloat16 h = __float2bfloat16(w);
        __nv_bfloat16 l = __float2bfloat16(w - __bfloat162float(h));
        oh[i] = h;
        ol[i] = l;
    }
}

// ---------------- HMMA bf16-split GEMM (M=64 tile, 256 thr / 8 warps, up to 2 products) ----------------
__device__ __forceinline__ void mma16816v(float* d, const uint32_t* a, const uint32_t* b) {
    asm volatile(
        "mma.sync.aligned.m16n8k16.row.col.f32.bf16.bf16.f32 "
        "{%0,%1,%2,%3}, {%4,%5,%6,%7}, {%8,%9}, {%0,%1,%2,%3};"
        : "+f"(d[0]), "+f"(d[1]), "+f"(d[2]), "+f"(d[3])
        : "r"(a[0]), "r"(a[1]), "r"(a[2]), "r"(a[3]), "r"(b[0]), "r"(b[1]));
}

// smem: A planes 2 x 64 x APITCH, B planes 2 x 128 x APITCH  (bf16)
#define SM2_BYTES ((2 * 64 + 2 * 128) * APITCH * 2)

__global__ void __launch_bounds__(256, 2)
mma_gemm2_k(const float* __restrict__ A,
            const __nv_bfloat16* __restrict__ Wh0, const __nv_bfloat16* __restrict__ Wl0,
            __half* __restrict__ C0, const float* __restrict__ bias,
            const float* __restrict__ epsp,
            const __nv_bfloat16* __restrict__ Wh1, const __nv_bfloat16* __restrict__ Wl1,
            __half* __restrict__ C1, int n) {
    extern __shared__ __nv_bfloat16 smem[];
    __nv_bfloat16* As_h = smem;                        // [64][APITCH]
    __nv_bfloat16* As_l = As_h + 64 * APITCH;
    __nv_bfloat16* Bs_h = As_l + 64 * APITCH;          // [128][APITCH]
    __nv_bfloat16* Bs_l = Bs_h + 128 * APITCH;

    const int tid = threadIdx.x;                       // 256 threads, 8 warps
    const int br = blockIdx.x * 64;
    const int wid = tid >> 5, lane = tid & 31;
    const int wm = (wid & 1) * 32;                     // 2 warps in m (32 rows each)
    const int wn = (wid >> 1) * 32;                    // 4 warps in n (32 cols each)
    const int g = lane >> 2;
    const int tg = lane & 3;

    // ---- load A tile (64 x 128 fp32) and split to bf16 hi/lo (once, reused by both products) ----
    for (int i = tid; i < 2048; i += 256) {
        int row = i >> 5;
        int c4 = (i & 31) << 2;
        int gr = br + row;
        float4 v = make_float4(0.f, 0.f, 0.f, 0.f);
        if (gr < n) v = *(const float4*)(A + (size_t)gr * DIM + c4);
        __nv_bfloat16 h0 = __float2bfloat16(v.x), h1 = __float2bfloat16(v.y);
        __nv_bfloat16 h2 = __float2bfloat16(v.z), h3 = __float2bfloat16(v.w);
        __nv_bfloat16 l0 = __float2bfloat16(v.x - __bfloat162float(h0));
        __nv_bfloat16 l1 = __float2bfloat16(v.y - __bfloat162float(h1));
        __nv_bfloat16 l2 = __float2bfloat16(v.z - __bfloat162float(h2));
        __nv_bfloat16 l3 = __float2bfloat16(v.w - __bfloat162float(h3));
        __nv_bfloat162 hA(h0, h1), hB(h2, h3), lA(l0, l1), lB(l2, l3);
        uint2 hu, lu;
        hu.x = *(uint32_t*)&hA; hu.y = *(uint32_t*)&hB;
        lu.x = *(uint32_t*)&lA; lu.y = *(uint32_t*)&lB;
        *(uint2*)&As_h[row * APITCH + c4] = hu;
        *(uint2*)&As_l[row * APITCH + c4] = lu;
    }

    const int nprod = (Wh1 != nullptr) ? 2 : 1;
    for (int p = 0; p < nprod; p++) {
        const __nv_bfloat16* Wh = p ? Wh1 : Wh0;
        const __nv_bfloat16* Wl = p ? Wl1 : Wl0;
        __half* C = p ? C1 : C0;

        // ---- load B planes (128 x 128 bf16) ----
        __syncthreads();   // protects As on p=0, previous-product Bs reads on p=1
        for (int i = tid; i < 128 * 16; i += 256) {
            int row = i >> 4;
            int c8 = (i & 15) << 3;
            *(uint4*)&Bs_h[row * APITCH + c8] = *(const uint4*)(Wh + row * DIM + c8);
            *(uint4*)&Bs_l[row * APITCH + c8] = *(const uint4*)(Wl + row * DIM + c8);
        }
        __syncthreads();

        float acc[2][4][4];
#pragma unroll
        for (int mt = 0; mt < 2; mt++)
#pragma unroll
            for (int nt = 0; nt < 4; nt++)
#pragma unroll
                for (int j = 0; j < 4; j++) acc[mt][nt][j] = 0.f;

#pragma unroll
        for (int kc = 0; kc < 8; kc++) {
            const int kb = kc * 16 + tg * 2;
            uint32_t ah[2][4], al[2][4], bh[4][2], bl[4][2];
#pragma unroll
            for (int mt = 0; mt < 2; mt++) {
                int r = wm + mt * 16 + g;
                ah[mt][0] = *(const uint32_t*)&As_h[r * APITCH + kb];
                ah[mt][1] = *(const uint32_t*)&As_h[(r + 8) * APITCH + kb];
                ah[mt][2] = *(const uint32_t*)&As_h[r * APITCH + kb + 8];
                ah[mt][3] = *(const uint32_t*)&As_h[(r + 8) * APITCH + kb + 8];
                al[mt][0] = *(const uint32_t*)&As_l[r * APITCH + kb];
                al[mt][1] = *(const uint32_t*)&As_l[(r + 8) * APITCH + kb];
                al[mt][2] = *(const uint32_t*)&As_l[r * APITCH + kb + 8];
                al[mt][3] = *(const uint32_t*)&As_l[(r + 8) * APITCH + kb + 8];
            }
#pragma unroll
            for (int nt = 0; nt < 4; nt++) {
                int r = wn + nt * 8 + g;
                bh[nt][0] = *(const uint32_t*)&Bs_h[r * APITCH + kb];
                bh[nt][1] = *(const uint32_t*)&Bs_h[r * APITCH + kb + 8];
                bl[nt][0] = *(const uint32_t*)&Bs_l[r * APITCH + kb];
                bl[nt][1] = *(const uint32_t*)&Bs_l[r * APITCH + kb + 8];
            }
#pragma unroll
            for (int mt = 0; mt < 2; mt++)
#pragma unroll
                for (int nt = 0; nt < 4; nt++) {
                    mma16816v(acc[mt][nt], ah[mt], bh[nt]);
                    mma16816v(acc[mt][nt], ah[mt], bl[nt]);
                    mma16816v(acc[mt][nt], al[mt], bh[nt]);
                }
        }

        // ---- epilogue (fp16 store) ----
        const bool biased = (p == 0) && (bias != nullptr);
        float esc = 1.0f;
        if (biased) esc = 1.0f + *epsp;
#pragma unroll
        for (int mt = 0; mt < 2; mt++) {
#pragma unroll
            for (int nt = 0; nt < 4; nt++) {
                int col = wn + nt * 8 + tg * 2;
                int r0 = br + wm + mt * 16 + g;
                float v0 = acc[mt][nt][0], v1 = acc[mt][nt][1];
                float v2 = acc[mt][nt][2], v3 = acc[mt][nt][3];
                if (biased) {
                    float b0 = bias[col], b1 = bias[col + 1];
                    v0 = esc * fmaxf(v0 + b0, 0.f);
                    v1 = esc * fmaxf(v1 + b1, 0.f);
                    v2 = esc * fmaxf(v2 + b0, 0.f);
                    v3 = esc * fmaxf(v3 + b1, 0.f);
                }
                if (r0 < n)     *(__half2*)(C + (size_t)r0 * DIM + col)       = __floats2half2_rn(v0, v1);
                if (r0 + 8 < n) *(__half2*)(C + (size_t)(r0 + 8) * DIM + col) = __floats2half2_rn(v2, v3);
            }
        }
    }
}

// ---------------- fused aggregation + epilogue (fp16 gather, fp32 accumulate) ----------------
__device__ __forceinline__ float4 relu4(float4 v) {
    return make_float4(fmaxf(v.x, 0.f), fmaxf(v.y, 0.f), fmaxf(v.z, 0.f), fmaxf(v.w, 0.f));
}
__device__ __forceinline__ void add4(float4& a, const float4 b) {
    a.x += b.x; a.y += b.y; a.z += b.z; a.w += b.w;
}
__device__ __forceinline__ void addh4(float4& a, uint2 u) {
    float2 f0 = __half22float2(*(__half2*)&u.x);
    float2 f1 = __half22float2(*(__half2*)&u.y);
    a.x += f0.x; a.y += f0.y; a.z += f1.x; a.w += f1.y;
}

__global__ void aggregate_k(const float* __restrict__ xt, const __half* __restrict__ souts,
                            const __half* __restrict__ z1, const __half* __restrict__ z2,
                            const __half* __restrict__ z3, const float* __restrict__ bk_t,
                            int kmax, float* __restrict__ xnext, int n) {
    int warp = (blockIdx.x * blockDim.x + threadIdx.x) >> 5;
    if (warp >= n) return;
    int lane = threadIdx.x & 31;

    float4 acc1 = make_float4(0.f, 0.f, 0.f, 0.f);
    float4 acc2 = acc1, acc3 = acc1;

    int beg = g_rowptr[warp];
    int deg = g_rowptr[warp + 1] - beg;
    const int le = lane * 4;

    for (int base = 0; base < deg; base += 32) {
        int m = min(32, deg - base);
        unsigned ew = 0;
        if (base + lane < deg) ew = g_edges[beg + base + lane];
        for (int i = 0; i < m; i++) {
            unsigned p = __shfl_sync(0xffffffffu, ew, i);
            int a = (int)(p >> 16);
            if (a > kmax) continue;
            int src = (int)(p & 0xFFFFu);
            const __half* zp = (a == 1) ? z1 : (a == 2) ? z2 : z3;
            uint2 u = *(const uint2*)(zp + (size_t)src * DIM + le);
            if (a == 1) addh4(acc1, u);
            else if (a == 2) addh4(acc2, u);
            else addh4(acc3, u);
        }
    }

    float4 o = make_float4(0.f, 0.f, 0.f, 0.f);
    addh4(o, *(const uint2*)(souts + (size_t)warp * DIM + le));
    {
        float4 b = ((const float4*)(bk_t + 0 * DIM))[lane];
        add4(acc1, b);
        add4(o, relu4(acc1));
    }
    if (kmax >= 2) {
        float4 b = ((const float4*)(bk_t + 1 * DIM))[lane];
        add4(acc2, b);
        add4(o, relu4(acc2));
    }
    if (kmax >= 3) {
        float4 b = ((const float4*)(bk_t + 2 * DIM))[lane];
        add4(acc3, b);
        add4(o, relu4(acc3));
    }
    float4 xv = ((const float4*)xt)[(size_t)warp * 32 + lane];
    float4 h = relu4(o);
    add4(xv, h);
    ((float4*)xnext)[(size_t)warp * 32 + lane] = xv;
}

// ---------------- launch ----------------
extern "C" void kernel_launch(void* const* d_in, const int* in_sizes, int n_in,
                              void* d_out, int out_size) {
    const float* x   = (const float*)d_in[0];
    const int*   ei  = (const int*)d_in[1];   // [2, E]
    const int*   ea  = (const int*)d_in[2];   // [E]
    const float* Ws  = (const float*)d_in[3];
    const float* bs  = (const float*)d_in[4];
    const float* Wk  = (const float*)d_in[5];
    const float* bk  = (const float*)d_in[6];
    const float* eps = (const float*)d_in[7];
    float* out = (float*)d_out;

    int n = in_sizes[0] / DIM;
    int e = in_sizes[2];
    const int* src = ei;
    const int* dst = ei + e;

    float *p_x1, *p_x2;
    __half *p_sout, *p_z0, *p_z1, *p_z2;
    cudaGetSymbolAddress((void**)&p_x1, g_x1);
    cudaGetSymbolAddress((void**)&p_x2, g_x2);
    cudaGetSymbolAddress((void**)&p_sout, g_sout);
    cudaGetSymbolAddress((void**)&p_z0, g_z0);
    cudaGetSymbolAddress((void**)&p_z1, g_z1);
    cudaGetSymbolAddress((void**)&p_z2, g_z2);
    __nv_bfloat16 *p_wh, *p_wl;
    cudaGetSymbolAddress((void**)&p_wh, g_whT);
    cudaGetSymbolAddress((void**)&p_wl, g_wlT);

    cudaFuncSetAttribute(mma_gemm2_k, cudaFuncAttributeMaxDynamicSharedMemorySize, SM2_BYTES);

    // ----- weight preprocessing + CSR build -----
    convw_k<<<12, 256>>>(Ws, Wk);
    zero_count_k<<<(n + 255) / 256, 256>>>(n);
    count_k<<<(e + 255) / 256, 256>>>(dst, e);
    int nb = (n + 1023) / 1024;
    scan1_k<<<nb, 256>>>(n);
    scan2_k<<<1, 64>>>(nb);
    scan3_k<<<(n + 255) / 256, 256>>>(n, e);
    place_k<<<(e + 255) / 256, 256>>>(src, dst, ea, e);

    const float* xs[4];
    xs[0] = x;
    xs[1] = p_x1;
    xs[2] = p_x2;
    xs[3] = out;

    int gemm_grid = (n + 63) / 64;
    int agg_grid = (n * 32 + 255) / 256;
    __half* zbuf[3] = {p_z0, p_z1, p_z2};

    for (int t = 0; t < LAY; t++) {
        // combined launch: sout = (1+eps)*relu(xt@Ws[t]+bs[t])  AND  z0 = xt@Wk[t][0]
        int slot1 = 3 + t * LAY + 0;
        mma_gemm2_k<<<gemm_grid, 256, SM2_BYTES>>>(
            xs[t],
            p_wh + (size_t)t * DIM * DIM, p_wl + (size_t)t * DIM * DIM, p_sout,
            bs + t * DIM, eps + t,
            p_wh + (size_t)slot1 * DIM * DIM, p_wl + (size_t)slot1 * DIM * DIM, zbuf[0],
            n);
        // remaining z_k (k >= 2) each use a different A -> single-product launches
        for (int k = 2; k <= t + 1; k++) {
            int slot = 3 + t * LAY + (k - 1);
            mma_gemm2_k<<<gemm_grid, 256, SM2_BYTES>>>(
                xs[t - (k - 1)],
                p_wh + (size_t)slot * DIM * DIM, p_wl + (size_t)slot * DIM * DIM, zbuf[k - 1],
                nullptr, nullptr,
                nullptr, nullptr, nullptr,
                n);
        }
        aggregate_k<<<agg_grid, 256>>>(xs[t], p_sout, p_z0, p_z1, p_z2,
                                       bk + (size_t)t * LAY * DIM, t + 1,
                                       (float*)xs[t + 1], n);
    }
}

// round 14
// speedup vs baseline: 1.1364x; 1.1364x over previous
#include <cuda_runtime.h>
#include <cuda_bf16.h>
#include <cuda_fp16.h>
#include <cstdint>

// Problem constants (DRewGIN: N=50000 nodes, E=800000 edges, D=128, L=3)
#define NMAX 50000
#define EMAX 800000
#define DIM  128
#define LAY  3
#define APITCH 136   // smem row pitch in bf16 elements (272 B -> conflict-free frag loads)

// ---------------- device scratch (static, no allocation) ----------------
__device__ float g_x1[NMAX * DIM];
__device__ float g_x2[NMAX * DIM];
__device__ __half g_sout[NMAX * DIM];   // fp16: halves gather-side L2 traffic
__device__ __half g_z0[NMAX * DIM];
__device__ __half g_z1[NMAX * DIM];
__device__ __half g_z2[NMAX * DIM];
__device__ __nv_bfloat16 g_whT[12 * DIM * DIM];  // weight^T hi planes [n][k]
__device__ __nv_bfloat16 g_wlT[12 * DIM * DIM];  // weight^T lo planes [n][k]
__device__ int g_count[NMAX + 64];
__device__ int g_rowptr[NMAX + 1];
__device__ int g_wptr[NMAX];
__device__ int g_bsum[64];
__device__ int g_boff[64];
__device__ unsigned g_edges[EMAX];   // packed: src (16b) | attr<<16

// ---------------- CSR build ----------------
__global__ void zero_count_k(int n) {
    int i = blockIdx.x * blockDim.x + threadIdx.x;
    if (i < n) g_count[i] = 0;
}
__global__ void count_k(const int* __restrict__ dst, int e) {
    int i = blockIdx.x * blockDim.x + threadIdx.x;
    if (i < e) atomicAdd(&g_count[dst[i]], 1);
}

__global__ void scan1_k(int n) {
    __shared__ int wsum[8];
    const int tid = threadIdx.x;               // 256 threads
    const int base = blockIdx.x * 1024 + tid * 4;
    int4 c = make_int4(0, 0, 0, 0);
    if (base < n) c = *(const int4*)&g_count[base];
    int s0 = c.x;
    int s1 = s0 + c.y;
    int s2 = s1 + c.z;
    int s3 = s2 + c.w;
    int lane = tid & 31, wid = tid >> 5;
    int v = s3;
#pragma unroll
    for (int off = 1; off < 32; off <<= 1) {
        int u = __shfl_up_sync(0xffffffffu, v, off);
        if (lane >= off) v += u;
    }
    if (lane == 31) wsum[wid] = v;
    __syncthreads();
    if (wid == 0) {
        int w = (lane < 8) ? wsum[lane] : 0;
#pragma unroll
        for (int off = 1; off < 8; off <<= 1) {
            int u = __shfl_up_sync(0xffffffffu, w, off);
            if (lane >= off) w += u;
        }
        if (lane < 8) wsum[lane] = w;
        if (lane == 7) g_bsum[blockIdx.x] = w;
    }
    __syncthreads();
    int excl = v - s3 + (wid ? wsum[wid - 1] : 0);
    if (base < n) {
        g_rowptr[base + 0] = excl;
        g_rowptr[base + 1] = excl + s0;
        g_rowptr[base + 2] = excl + s1;
        g_rowptr[base + 3] = excl + s2;
    }
}
__global__ void scan2_k(int nb) {
    int tid = threadIdx.x;   // 64
    int v = (tid < nb) ? g_bsum[tid] : 0;
    __shared__ int sh[64];
    sh[tid] = v;
    __syncthreads();
    for (int off = 1; off < 64; off <<= 1) {
        int u = (tid >= off) ? sh[tid - off] : 0;
        __syncthreads();
        sh[tid] += u;
        __syncthreads();
    }
    if (tid < nb) g_boff[tid] = sh[tid] - v;
}
__global__ void scan3_k(int n, int e) {
    int i = blockIdx.x * blockDim.x + threadIdx.x;
    if (i < n) {
        int r = g_rowptr[i] + g_boff[i >> 10];
        g_rowptr[i] = r;
        g_wptr[i] = r;
    }
    if (i == 0) g_rowptr[n] = e;
}

__global__ void place_k(const int* __restrict__ src, const int* __restrict__ dst,
                        const int* __restrict__ attr, int e) {
    int i = blockIdx.x * blockDim.x + threadIdx.x;
    if (i < e) {
        int pos = atomicAdd(&g_wptr[dst[i]], 1);
        g_edges[pos] = (unsigned)src[i] | ((unsigned)attr[i] << 16);
    }
}

// ---------------- weight preprocessing: transpose + bf16 split ----------------
__global__ void convw_k(const float* __restrict__ Ws, const float* __restrict__ Wk) {
    int slot = blockIdx.x;
    const float* W = (slot < 3) ? (Ws + (size_t)slot * DIM * DIM)
                                : (Wk + (size_t)(slot - 3) * DIM * DIM);
    __nv_bfloat16* oh = g_whT + (size_t)slot * DIM * DIM;
    __nv_bfloat16* ol = g_wlT + (size_t)slot * DIM * DIM;
    for (int i = threadIdx.x; i < DIM * DIM; i += blockDim.x) {
        int nn = i >> 7, kk = i & 127;
        float w = W[kk * DIM + nn];
        __nv_bfloat16 h = __float2bfloat16(w);
        __nv_bfloat16 l = __float2bfloat16(w - __bfloat162float(h));
        oh[i] = h;
        ol[i] = l;
    }
}

// ---------------- HMMA bf16-split GEMM (R11 core: 128 thr, warp tile 32x64) ----------------
__device__ __forceinline__ void mma16816v(float* d, const uint32_t* a, const uint32_t* b) {
    asm volatile(
        "mma.sync.aligned.m16n8k16.row.col.f32.bf16.bf16.f32 "
        "{%0,%1,%2,%3}, {%4,%5,%6,%7}, {%8,%9}, {%0,%1,%2,%3};"
        : "+f"(d[0]), "+f"(d[1]), "+f"(d[2]), "+f"(d[3])
        : "r"(a[0]), "r"(a[1]), "r"(a[2]), "r"(a[3]), "r"(b[0]), "r"(b[1]));
}

// smem: A planes 2 x 64 x APITCH, B planes 2 x 128 x APITCH  (bf16)
#define SM2_BYTES ((2 * 64 + 2 * 128) * APITCH * 2)

__device__ __forceinline__ void load_A_split(const float* __restrict__ A, int br, int n,
                                             __nv_bfloat16* As_h, __nv_bfloat16* As_l,
                                             int tid) {
    for (int i = tid; i < 2048; i += 128) {
        int row = i >> 5;
        int c4 = (i & 31) << 2;
        int gr = br + row;
        float4 v = make_float4(0.f, 0.f, 0.f, 0.f);
        if (gr < n) v = *(const float4*)(A + (size_t)gr * DIM + c4);
        __nv_bfloat16 h0 = __float2bfloat16(v.x), h1 = __float2bfloat16(v.y);
        __nv_bfloat16 h2 = __float2bfloat16(v.z), h3 = __float2bfloat16(v.w);
        __nv_bfloat16 l0 = __float2bfloat16(v.x - __bfloat162float(h0));
        __nv_bfloat16 l1 = __float2bfloat16(v.y - __bfloat162float(h1));
        __nv_bfloat16 l2 = __float2bfloat16(v.z - __bfloat162float(h2));
        __nv_bfloat16 l3 = __float2bfloat16(v.w - __bfloat162float(h3));
        __nv_bfloat162 hA(h0, h1), hB(h2, h3), lA(l0, l1), lB(l2, l3);
        uint2 hu, lu;
        hu.x = *(uint32_t*)&hA; hu.y = *(uint32_t*)&hB;
        lu.x = *(uint32_t*)&lA; lu.y = *(uint32_t*)&lB;
        *(uint2*)&As_h[row * APITCH + c4] = hu;
        *(uint2*)&As_l[row * APITCH + c4] = lu;
    }
}
__device__ __forceinline__ void load_B(const __nv_bfloat16* __restrict__ Wh,
                                       const __nv_bfloat16* __restrict__ Wl,
                                       __nv_bfloat16* Bs_h, __nv_bfloat16* Bs_l, int tid) {
    for (int i = tid; i < 128 * 16; i += 128) {
        int row = i >> 4;
        int c8 = (i & 15) << 3;
        *(uint4*)&Bs_h[row * APITCH + c8] = *(const uint4*)(Wh + row * DIM + c8);
        *(uint4*)&Bs_l[row * APITCH + c8] = *(const uint4*)(Wl + row * DIM + c8);
    }
}

// R11 inner core: 4 warps = 2(m: 32 rows) x 2(n: 64 cols)
__device__ __forceinline__ void gemm_core(const __nv_bfloat16* As_h, const __nv_bfloat16* As_l,
                                          const __nv_bfloat16* Bs_h, const __nv_bfloat16* Bs_l,
                                          __half* __restrict__ C, const float* bias,
                                          const float* epsp, int br, int n, int tid) {
    const int wid = tid >> 5, lane = tid & 31;
    const int wm = (wid & 1) * 32;
    const int wn = (wid >> 1) * 64;
    const int g = lane >> 2;
    const int tg = lane & 3;

    float acc[2][8][4];
#pragma unroll
    for (int mt = 0; mt < 2; mt++)
#pragma unroll
        for (int nt = 0; nt < 8; nt++)
#pragma unroll
            for (int j = 0; j < 4; j++) acc[mt][nt][j] = 0.f;

#pragma unroll
    for (int kc = 0; kc < 8; kc++) {
        const int kb = kc * 16 + tg * 2;
        uint32_t ah[2][4], al[2][4], bh[8][2], bl[8][2];
#pragma unroll
        for (int mt = 0; mt < 2; mt++) {
            int r = wm + mt * 16 + g;
            ah[mt][0] = *(const uint32_t*)&As_h[r * APITCH + kb];
            ah[mt][1] = *(const uint32_t*)&As_h[(r + 8) * APITCH + kb];
            ah[mt][2] = *(const uint32_t*)&As_h[r * APITCH + kb + 8];
            ah[mt][3] = *(const uint32_t*)&As_h[(r + 8) * APITCH + kb + 8];
            al[mt][0] = *(const uint32_t*)&As_l[r * APITCH + kb];
            al[mt][1] = *(const uint32_t*)&As_l[(r + 8) * APITCH + kb];
            al[mt][2] = *(const uint32_t*)&As_l[r * APITCH + kb + 8];
            al[mt][3] = *(const uint32_t*)&As_l[(r + 8) * APITCH + kb + 8];
        }
#pragma unroll
        for (int nt = 0; nt < 8; nt++) {
            int r = wn + nt * 8 + g;
            bh[nt][0] = *(const uint32_t*)&Bs_h[r * APITCH + kb];
            bh[nt][1] = *(const uint32_t*)&Bs_h[r * APITCH + kb + 8];
            bl[nt][0] = *(const uint32_t*)&Bs_l[r * APITCH + kb];
            bl[nt][1] = *(const uint32_t*)&Bs_l[r * APITCH + kb + 8];
        }
#pragma unroll
        for (int mt = 0; mt < 2; mt++)
#pragma unroll
            for (int nt = 0; nt < 8; nt++) {
                mma16816v(acc[mt][nt], ah[mt], bh[nt]);
                mma16816v(acc[mt][nt], ah[mt], bl[nt]);
                mma16816v(acc[mt][nt], al[mt], bh[nt]);
            }
    }

    // ---- epilogue (fp16 store) ----
    const bool biased = (bias != nullptr);
    float esc = 1.0f;
    if (biased) esc = 1.0f + *epsp;
#pragma unroll
    for (int mt = 0; mt < 2; mt++) {
#pragma unroll
        for (int nt = 0; nt < 8; nt++) {
            int col = wn + nt * 8 + tg * 2;
            int r0 = br + wm + mt * 16 + g;
            float v0 = acc[mt][nt][0], v1 = acc[mt][nt][1];
            float v2 = acc[mt][nt][2], v3 = acc[mt][nt][3];
            if (biased) {
                float b0 = bias[col], b1 = bias[col + 1];
                v0 = esc * fmaxf(v0 + b0, 0.f);
                v1 = esc * fmaxf(v1 + b1, 0.f);
                v2 = esc * fmaxf(v2 + b0, 0.f);
                v3 = esc * fmaxf(v3 + b1, 0.f);
            }
            if (r0 < n)     *(__half2*)(C + (size_t)r0 * DIM + col)       = __floats2half2_rn(v0, v1);
            if (r0 + 8 < n) *(__half2*)(C + (size_t)(r0 + 8) * DIM + col) = __floats2half2_rn(v2, v3);
        }
    }
}

// dual-product kernel: shared A (loaded/split once), C0 (bias+eps) and optional C1
__global__ void __launch_bounds__(128, 2)
mma_gemm2_k(const float* __restrict__ A,
            const __nv_bfloat16* __restrict__ Wh0, const __nv_bfloat16* __restrict__ Wl0,
            __half* __restrict__ C0, const float* __restrict__ bias,
            const float* __restrict__ epsp,
            const __nv_bfloat16* __restrict__ Wh1, const __nv_bfloat16* __restrict__ Wl1,
            __half* __restrict__ C1, int n) {
    extern __shared__ __nv_bfloat16 smem[];
    __nv_bfloat16* As_h = smem;
    __nv_bfloat16* As_l = As_h + 64 * APITCH;
    __nv_bfloat16* Bs_h = As_l + 64 * APITCH;
    __nv_bfloat16* Bs_l = Bs_h + 128 * APITCH;

    const int tid = threadIdx.x;
    const int br = blockIdx.x * 64;

    load_A_split(A, br, n, As_h, As_l, tid);

    const int nprod = (Wh1 != nullptr) ? 2 : 1;
    for (int p = 0; p < nprod; p++) {
        __syncthreads();   // protects As on p=0, prev-product Bs reads on p=1
        load_B(p ? Wh1 : Wh0, p ? Wl1 : Wl0, Bs_h, Bs_l, tid);
        __syncthreads();
        gemm_core(As_h, As_l, Bs_h, Bs_l, p ? C1 : C0,
                  p ? nullptr : bias, epsp, br, n, tid);
    }
}

// batched independent single products (grid.y selects which), no bias
struct GemmSingles {
    const float* A[2];
    const __nv_bfloat16* Wh[2];
    const __nv_bfloat16* Wl[2];
    __half* C[2];
};
__global__ void __launch_bounds__(128, 2)
mma_gemmb_k(GemmSingles gs, int n) {
    extern __shared__ __nv_bfloat16 smem[];
    __nv_bfloat16* As_h = smem;
    __nv_bfloat16* As_l = As_h + 64 * APITCH;
    __nv_bfloat16* Bs_h = As_l + 64 * APITCH;
    __nv_bfloat16* Bs_l = Bs_h + 128 * APITCH;

    const int tid = threadIdx.x;
    const int br = blockIdx.x * 64;
    const int p = blockIdx.y;

    load_A_split(gs.A[p], br, n, As_h, As_l, tid);
    load_B(gs.Wh[p], gs.Wl[p], Bs_h, Bs_l, tid);
    __syncthreads();
    gemm_core(As_h, As_l, Bs_h, Bs_l, gs.C[p], nullptr, nullptr, br, n, tid);
}

// ---------------- fused aggregation + epilogue (fp16 gather, fp32 accumulate) ----------------
__device__ __forceinline__ float4 relu4(float4 v) {
    return make_float4(fmaxf(v.x, 0.f), fmaxf(v.y, 0.f), fmaxf(v.z, 0.f), fmaxf(v.w, 0.f));
}
__device__ __forceinline__ void add4(float4& a, const float4 b) {
    a.x += b.x; a.y += b.y; a.z += b.z; a.w += b.w;
}
__device__ __forceinline__ void addh4(float4& a, uint2 u) {
    float2 f0 = __half22float2(*(__half2*)&u.x);
    float2 f1 = __half22float2(*(__half2*)&u.y);
    a.x += f0.x; a.y += f0.y; a.z += f1.x; a.w += f1.y;
}

__global__ void aggregate_k(const float* __restrict__ xt, const __half* __restrict__ souts,
                            const __half* __restrict__ z1, const __half* __restrict__ z2,
                            const __half* __restrict__ z3, const float* __restrict__ bk_t,
                            int kmax, float* __restrict__ xnext, int n) {
    int warp = (blockIdx.x * blockDim.x + threadIdx.x) >> 5;
    if (warp >= n) return;
    int lane = threadIdx.x & 31;

    float4 acc1 = make_float4(0.f, 0.f, 0.f, 0.f);
    float4 acc2 = acc1, acc3 = acc1;

    int beg = g_rowptr[warp];
    int deg = g_rowptr[warp + 1] - beg;
    const int le = lane * 4;

    for (int base = 0; base < deg; base += 32) {
        int m = min(32, deg - base);
        unsigned ew = 0;
        if (base + lane < deg) ew = g_edges[beg + base + lane];
        for (int i = 0; i < m; i++) {
            unsigned p = __shfl_sync(0xffffffffu, ew, i);
            int a = (int)(p >> 16);
            if (a > kmax) continue;
            int src = (int)(p & 0xFFFFu);
            const __half* zp = (a == 1) ? z1 : (a == 2) ? z2 : z3;
            uint2 u = *(const uint2*)(zp + (size_t)src * DIM + le);
            if (a == 1) addh4(acc1, u);
            else if (a == 2) addh4(acc2, u);
            else addh4(acc3, u);
        }
    }

    float4 o = make_float4(0.f, 0.f, 0.f, 0.f);
    addh4(o, *(const uint2*)(souts + (size_t)warp * DIM + le));
    {
        float4 b = ((const float4*)(bk_t + 0 * DIM))[lane];
        add4(acc1, b);
        add4(o, relu4(acc1));
    }
    if (kmax >= 2) {
        float4 b = ((const float4*)(bk_t + 1 * DIM))[lane];
        add4(acc2, b);
        add4(o, relu4(acc2));
    }
    if (kmax >= 3) {
        float4 b = ((const float4*)(bk_t + 2 * DIM))[lane];
        add4(acc3, b);
        add4(o, relu4(acc3));
    }
    float4 xv = ((const float4*)xt)[(size_t)warp * 32 + lane];
    float4 h = relu4(o);
    add4(xv, h);
    ((float4*)xnext)[(size_t)warp * 32 + lane] = xv;
}

// ---------------- launch ----------------
extern "C" void kernel_launch(void* const* d_in, const int* in_sizes, int n_in,
                              void* d_out, int out_size) {
    const float* x   = (const float*)d_in[0];
    const int*   ei  = (const int*)d_in[1];   // [2, E]
    const int*   ea  = (const int*)d_in[2];   // [E]
    const float* Ws  = (const float*)d_in[3];
    const float* bs  = (const float*)d_in[4];
    const float* Wk  = (const float*)d_in[5];
    const float* bk  = (const float*)d_in[6];
    const float* eps = (const float*)d_in[7];
    float* out = (float*)d_out;

    int n = in_sizes[0] / DIM;
    int e = in_sizes[2];
    const int* src = ei;
    const int* dst = ei + e;

    float *p_x1, *p_x2;
    __half *p_sout, *p_z0, *p_z1, *p_z2;
    cudaGetSymbolAddress((void**)&p_x1, g_x1);
    cudaGetSymbolAddress((void**)&p_x2, g_x2);
    cudaGetSymbolAddress((void**)&p_sout, g_sout);
    cudaGetSymbolAddress((void**)&p_z0, g_z0);
    cudaGetSymbolAddress((void**)&p_z1, g_z1);
    cudaGetSymbolAddress((void**)&p_z2, g_z2);
    __nv_bfloat16 *p_wh, *p_wl;
    cudaGetSymbolAddress((void**)&p_wh, g_whT);
    cudaGetSymbolAddress((void**)&p_wl, g_wlT);

    cudaFuncSetAttribute(mma_gemm2_k, cudaFuncAttributeMaxDynamicSharedMemorySize, SM2_BYTES);
    cudaFuncSetAttribute(mma_gemmb_k, cudaFuncAttributeMaxDynamicSharedMemorySize, SM2_BYTES);

    // ----- weight preprocessing + CSR build -----
    convw_k<<<12, 256>>>(Ws, Wk);
    zero_count_k<<<(n + 255) / 256, 256>>>(n);
    count_k<<<(e + 255) / 256, 256>>>(dst, e);
    int nb = (n + 1023) / 1024;
    scan1_k<<<nb, 256>>>(n);
    scan2_k<<<1, 64>>>(nb);
    scan3_k<<<(n + 255) / 256, 256>>>(n, e);
    place_k<<<(e + 255) / 256, 256>>>(src, dst, ea, e);

    const float* xs[4];
    xs[0] = x;
    xs[1] = p_x1;
    xs[2] = p_x2;
    xs[3] = out;

    int gemm_grid = (n + 63) / 64;
    int agg_grid = (n * 32 + 255) / 256;
    __half* zbuf[3] = {p_z0, p_z1, p_z2};

    for (int t = 0; t < LAY; t++) {
        // dual launch: sout = (1+eps)*relu(xt@Ws[t]+bs[t])  AND  z0 = xt@Wk[t][0] (shared A)
        int slot1 = 3 + t * LAY + 0;
        mma_gemm2_k<<<gemm_grid, 128, SM2_BYTES>>>(
            xs[t],
            p_wh + (size_t)t * DIM * DIM, p_wl + (size_t)t * DIM * DIM, p_sout,
            bs + t * DIM, eps + t,
            p_wh + (size_t)slot1 * DIM * DIM, p_wl + (size_t)slot1 * DIM * DIM, zbuf[0],
            n);
        // remaining z_k (k >= 2): independent A matrices -> one grid.y-batched launch
        if (t >= 1) {
            GemmSingles gs;
            for (int k = 2; k <= t + 1; k++) {
                int slot = 3 + t * LAY + (k - 1);
                gs.A[k - 2] = xs[t - (k - 1)];
                gs.Wh[k - 2] = p_wh + (size_t)slot * DIM * DIM;
                gs.Wl[k - 2] = p_wl + (size_t)slot * DIM * DIM;
                gs.C[k - 2] = zbuf[k - 1];
            }
            dim3 grid(gemm_grid, t, 1);
            mma_gemmb_k<<<grid, 128, SM2_BYTES>>>(gs, n);
        }
        aggregate_k<<<agg_grid, 256>>>(xs[t], p_sout, p_z0, p_z1, p_z2,
                                       bk + (size_t)t * LAY * DIM, t + 1,
                                       (float*)xs[t + 1], n);
    }
}

// round 15
// speedup vs baseline: 1.3076x; 1.1506x over previous
#include <cuda_runtime.h>
#include <cuda_bf16.h>
#include <cuda_fp16.h>
#include <cstdint>

// Problem constants (DRewGIN: N=50000 nodes, E=800000 edges, D=128, L=3)
#define NMAX 50000
#define EMAX 800000
#define DIM  128
#define LAY  3
#define APITCH 136   // smem row pitch in bf16 elements (272 B -> conflict-free frag loads)

// ---------------- device scratch (static, no allocation) ----------------
__device__ float g_x1[NMAX * DIM];
__device__ float g_x2[NMAX * DIM];
__device__ __half g_sout[NMAX * DIM];   // fp16: halves gather-side L2 traffic
__device__ __half g_z0[NMAX * DIM];
__device__ __half g_z1[NMAX * DIM];
__device__ __half g_z2[NMAX * DIM];
__device__ __nv_bfloat16 g_whT[12 * DIM * DIM];  // weight^T hi planes [n][k]
__device__ __nv_bfloat16 g_wlT[12 * DIM * DIM];  // weight^T lo planes [n][k]
__device__ int g_count[NMAX + 64];
__device__ int g_rowptr[NMAX + 1];
__device__ int g_wptr[NMAX];
__device__ int g_bsum[64];
__device__ int g_boff[64];
__device__ unsigned g_edges[EMAX];   // packed: src (16b) | attr<<16

// ---------------- CSR build ----------------
__global__ void count_k(const int* __restrict__ dst, int e) {
    int i = blockIdx.x * blockDim.x + threadIdx.x;
    if (i < e) atomicAdd(&g_count[dst[i]], 1);
}

__global__ void scan1_k(int n) {
    __shared__ int wsum[8];
    const int tid = threadIdx.x;               // 256 threads
    const int base = blockIdx.x * 1024 + tid * 4;
    int4 c = make_int4(0, 0, 0, 0);
    if (base < n) c = *(const int4*)&g_count[base];
    int s0 = c.x;
    int s1 = s0 + c.y;
    int s2 = s1 + c.z;
    int s3 = s2 + c.w;
    int lane = tid & 31, wid = tid >> 5;
    int v = s3;
#pragma unroll
    for (int off = 1; off < 32; off <<= 1) {
        int u = __shfl_up_sync(0xffffffffu, v, off);
        if (lane >= off) v += u;
    }
    if (lane == 31) wsum[wid] = v;
    __syncthreads();
    if (wid == 0) {
        int w = (lane < 8) ? wsum[lane] : 0;
#pragma unroll
        for (int off = 1; off < 8; off <<= 1) {
            int u = __shfl_up_sync(0xffffffffu, w, off);
            if (lane >= off) w += u;
        }
        if (lane < 8) wsum[lane] = w;
        if (lane == 7) g_bsum[blockIdx.x] = w;
    }
    __syncthreads();
    int excl = v - s3 + (wid ? wsum[wid - 1] : 0);
    if (base < n) {
        g_rowptr[base + 0] = excl;
        g_rowptr[base + 1] = excl + s0;
        g_rowptr[base + 2] = excl + s1;
        g_rowptr[base + 3] = excl + s2;
    }
}
__global__ void scan2_k(int nb) {
    int tid = threadIdx.x;   // 64
    int v = (tid < nb) ? g_bsum[tid] : 0;
    __shared__ int sh[64];
    sh[tid] = v;
    __syncthreads();
    for (int off = 1; off < 64; off <<= 1) {
        int u = (tid >= off) ? sh[tid - off] : 0;
        __syncthreads();
        sh[tid] += u;
        __syncthreads();
    }
    if (tid < nb) g_boff[tid] = sh[tid] - v;
}
__global__ void scan3_k(int n, int e) {
    int i = blockIdx.x * blockDim.x + threadIdx.x;
    if (i < n) {
        int r = g_rowptr[i] + g_boff[i >> 10];
        g_rowptr[i] = r;
        g_wptr[i] = r;
    }
    if (i == 0) g_rowptr[n] = e;
}

__global__ void place_k(const int* __restrict__ src, const int* __restrict__ dst,
                        const int* __restrict__ attr, int e) {
    int i = blockIdx.x * blockDim.x + threadIdx.x;
    if (i < e) {
        int pos = atomicAdd(&g_wptr[dst[i]], 1);
        g_edges[pos] = (unsigned)src[i] | ((unsigned)attr[i] << 16);
    }
}

// ---------------- weight preprocessing: tiled transpose + bf16 split ----------------
// grid (16 tiles, 12 slots); block 32x8. Coalesced read of W[kk][nn], coalesced
// write of W^T[nn][kk] via padded smem tile.
__global__ void convw_k(const float* __restrict__ Ws, const float* __restrict__ Wk) {
    __shared__ float sh[32][33];
    int slot = blockIdx.y;
    const float* W = (slot < 3) ? (Ws + (size_t)slot * DIM * DIM)
                                : (Wk + (size_t)(slot - 3) * DIM * DIM);
    __nv_bfloat16* oh = g_whT + (size_t)slot * DIM * DIM;
    __nv_bfloat16* ol = g_wlT + (size_t)slot * DIM * DIM;

    int ti = blockIdx.x >> 2;        // kk tile (0..3)
    int tj = blockIdx.x & 3;         // nn tile (0..3)
    int tx = threadIdx.x;            // 0..31
    int ty = threadIdx.y;            // 0..7

#pragma unroll
    for (int r = 0; r < 4; r++) {
        int kk = ti * 32 + ty + r * 8;
        int nn = tj * 32 + tx;
        sh[ty + r * 8][tx] = W[kk * DIM + nn];
    }
    __syncthreads();
#pragma unroll
    for (int r = 0; r < 4; r++) {
        int nn = tj * 32 + ty + r * 8;
        int kk = ti * 32 + tx;
        float w = sh[tx][ty + r * 8];
        __nv_bfloat16 h = __float2bfloat16(w);
        __nv_bfloat16 l = __float2bfloat16(w - __bfloat162float(h));
        oh[(size_t)nn * DIM + kk] = h;
        ol[(size_t)nn * DIM + kk] = l;
    }
}

// ---------------- HMMA bf16-split GEMM (M=64 tile, up to 2 products per launch) ----------------
__device__ __forceinline__ void mma16816v(float* d, const uint32_t* a, const uint32_t* b) {
    asm volatile(
        "mma.sync.aligned.m16n8k16.row.col.f32.bf16.bf16.f32 "
        "{%0,%1,%2,%3}, {%4,%5,%6,%7}, {%8,%9}, {%0,%1,%2,%3};"
        : "+f"(d[0]), "+f"(d[1]), "+f"(d[2]), "+f"(d[3])
        : "r"(a[0]), "r"(a[1]), "r"(a[2]), "r"(a[3]), "r"(b[0]), "r"(b[1]));
}

// smem: A planes 2 x 64 x APITCH, B planes 2 x 128 x APITCH  (bf16)
#define SM2_BYTES ((2 * 64 + 2 * 128) * APITCH * 2)

__global__ void __launch_bounds__(128, 2)
mma_gemm2_k(const float* __restrict__ A,
            const __nv_bfloat16* __restrict__ Wh0, const __nv_bfloat16* __restrict__ Wl0,
            __half* __restrict__ C0, const float* __restrict__ bias,
            const float* __restrict__ epsp,
            const __nv_bfloat16* __restrict__ Wh1, const __nv_bfloat16* __restrict__ Wl1,
            __half* __restrict__ C1, int n) {
    extern __shared__ __nv_bfloat16 smem[];
    __nv_bfloat16* As_h = smem;                        // [64][APITCH]
    __nv_bfloat16* As_l = As_h + 64 * APITCH;
    __nv_bfloat16* Bs_h = As_l + 64 * APITCH;          // [128][APITCH]
    __nv_bfloat16* Bs_l = Bs_h + 128 * APITCH;

    const int tid = threadIdx.x;                       // 128 threads
    const int br = blockIdx.x * 64;
    const int wid = tid >> 5, lane = tid & 31;
    const int wm = (wid & 1) * 32;                     // 2 warps in m
    const int wn = (wid >> 1) * 64;                    // 2 warps in n
    const int g = lane >> 2;
    const int tg = lane & 3;

    // ---- load A tile (64 x 128 fp32) and split to bf16 hi/lo (once, reused by both products) ----
    for (int i = tid; i < 2048; i += 128) {
        int row = i >> 5;
        int c4 = (i & 31) << 2;
        int gr = br + row;
        float4 v = make_float4(0.f, 0.f, 0.f, 0.f);
        if (gr < n) v = *(const float4*)(A + (size_t)gr * DIM + c4);
        __nv_bfloat16 h0 = __float2bfloat16(v.x), h1 = __float2bfloat16(v.y);
        __nv_bfloat16 h2 = __float2bfloat16(v.z), h3 = __float2bfloat16(v.w);
        __nv_bfloat16 l0 = __float2bfloat16(v.x - __bfloat162float(h0));
        __nv_bfloat16 l1 = __float2bfloat16(v.y - __bfloat162float(h1));
        __nv_bfloat16 l2 = __float2bfloat16(v.z - __bfloat162float(h2));
        __nv_bfloat16 l3 = __float2bfloat16(v.w - __bfloat162float(h3));
        __nv_bfloat162 hA(h0, h1), hB(h2, h3), lA(l0, l1), lB(l2, l3);
        uint2 hu, lu;
        hu.x = *(uint32_t*)&hA; hu.y = *(uint32_t*)&hB;
        lu.x = *(uint32_t*)&lA; lu.y = *(uint32_t*)&lB;
        *(uint2*)&As_h[row * APITCH + c4] = hu;
        *(uint2*)&As_l[row * APITCH + c4] = lu;
    }

    const int nprod = (Wh1 != nullptr) ? 2 : 1;
    for (int p = 0; p < nprod; p++) {
        const __nv_bfloat16* Wh = p ? Wh1 : Wh0;
        const __nv_bfloat16* Wl = p ? Wl1 : Wl0;
        __half* C = p ? C1 : C0;

        // ---- load B planes (128 x 128 bf16) ----
        __syncthreads();   // protects As on p=0, previous-product Bs reads on p=1
        for (int i = tid; i < 128 * 16; i += 128) {
            int row = i >> 4;
            int c8 = (i & 15) << 3;
            *(uint4*)&Bs_h[row * APITCH + c8] = *(const uint4*)(Wh + row * DIM + c8);
            *(uint4*)&Bs_l[row * APITCH + c8] = *(const uint4*)(Wl + row * DIM + c8);
        }
        __syncthreads();

        float acc[2][8][4];
#pragma unroll
        for (int mt = 0; mt < 2; mt++)
#pragma unroll
            for (int nt = 0; nt < 8; nt++)
#pragma unroll
                for (int j = 0; j < 4; j++) acc[mt][nt][j] = 0.f;

#pragma unroll
        for (int kc = 0; kc < 8; kc++) {
            const int kb = kc * 16 + tg * 2;
            uint32_t ah[2][4], al[2][4], bh[8][2], bl[8][2];
#pragma unroll
            for (int mt = 0; mt < 2; mt++) {
                int r = wm + mt * 16 + g;
                ah[mt][0] = *(const uint32_t*)&As_h[r * APITCH + kb];
                ah[mt][1] = *(const uint32_t*)&As_h[(r + 8) * APITCH + kb];
                ah[mt][2] = *(const uint32_t*)&As_h[r * APITCH + kb + 8];
                ah[mt][3] = *(const uint32_t*)&As_h[(r + 8) * APITCH + kb + 8];
                al[mt][0] = *(const uint32_t*)&As_l[r * APITCH + kb];
                al[mt][1] = *(const uint32_t*)&As_l[(r + 8) * APITCH + kb];
                al[mt][2] = *(const uint32_t*)&As_l[r * APITCH + kb + 8];
                al[mt][3] = *(const uint32_t*)&As_l[(r + 8) * APITCH + kb + 8];
            }
#pragma unroll
            for (int nt = 0; nt < 8; nt++) {
                int r = wn + nt * 8 + g;
                bh[nt][0] = *(const uint32_t*)&Bs_h[r * APITCH + kb];
                bh[nt][1] = *(const uint32_t*)&Bs_h[r * APITCH + kb + 8];
                bl[nt][0] = *(const uint32_t*)&Bs_l[r * APITCH + kb];
                bl[nt][1] = *(const uint32_t*)&Bs_l[r * APITCH + kb + 8];
            }
#pragma unroll
            for (int mt = 0; mt < 2; mt++)
#pragma unroll
                for (int nt = 0; nt < 8; nt++) {
                    mma16816v(acc[mt][nt], ah[mt], bh[nt]);
                    mma16816v(acc[mt][nt], ah[mt], bl[nt]);
                    mma16816v(acc[mt][nt], al[mt], bh[nt]);
                }
        }

        // ---- epilogue (fp16 store) ----
        const bool biased = (p == 0) && (bias != nullptr);
        float esc = 1.0f;
        if (biased) esc = 1.0f + *epsp;
#pragma unroll
        for (int mt = 0; mt < 2; mt++) {
#pragma unroll
            for (int nt = 0; nt < 8; nt++) {
                int col = wn + nt * 8 + tg * 2;
                int r0 = br + wm + mt * 16 + g;
                float v0 = acc[mt][nt][0], v1 = acc[mt][nt][1];
                float v2 = acc[mt][nt][2], v3 = acc[mt][nt][3];
                if (biased) {
                    float b0 = bias[col], b1 = bias[col + 1];
                    v0 = esc * fmaxf(v0 + b0, 0.f);
                    v1 = esc * fmaxf(v1 + b1, 0.f);
                    v2 = esc * fmaxf(v2 + b0, 0.f);
                    v3 = esc * fmaxf(v3 + b1, 0.f);
                }
                if (r0 < n)     *(__half2*)(C + (size_t)r0 * DIM + col)       = __floats2half2_rn(v0, v1);
                if (r0 + 8 < n) *(__half2*)(C + (size_t)(r0 + 8) * DIM + col) = __floats2half2_rn(v2, v3);
            }
        }
    }
}

// ---------------- fused aggregation + epilogue (fp16 gather, fp32 accumulate) ----------------
__device__ __forceinline__ float4 relu4(float4 v) {
    return make_float4(fmaxf(v.x, 0.f), fmaxf(v.y, 0.f), fmaxf(v.z, 0.f), fmaxf(v.w, 0.f));
}
__device__ __forceinline__ void add4(float4& a, const float4 b) {
    a.x += b.x; a.y += b.y; a.z += b.z; a.w += b.w;
}
__device__ __forceinline__ void addh4(float4& a, uint2 u) {
    float2 f0 = __half22float2(*(__half2*)&u.x);
    float2 f1 = __half22float2(*(__half2*)&u.y);
    a.x += f0.x; a.y += f0.y; a.z += f1.x; a.w += f1.y;
}

__global__ void aggregate_k(const float* __restrict__ xt, const __half* __restrict__ souts,
                            const __half* __restrict__ z1, const __half* __restrict__ z2,
                            const __half* __restrict__ z3, const float* __restrict__ bk_t,
                            int kmax, float* __restrict__ xnext, int n) {
    int warp = (blockIdx.x * blockDim.x + threadIdx.x) >> 5;
    if (warp >= n) return;
    int lane = threadIdx.x & 31;

    float4 acc1 = make_float4(0.f, 0.f, 0.f, 0.f);
    float4 acc2 = acc1, acc3 = acc1;

    int beg = g_rowptr[warp];
    int deg = g_rowptr[warp + 1] - beg;
    const int le = lane * 4;

    for (int base = 0; base < deg; base += 32) {
        int m = min(32, deg - base);
        unsigned ew = 0;
        if (base + lane < deg) ew = g_edges[beg + base + lane];
        for (int i = 0; i < m; i++) {
            unsigned p = __shfl_sync(0xffffffffu, ew, i);
            int a = (int)(p >> 16);
            if (a > kmax) continue;
            int src = (int)(p & 0xFFFFu);
            const __half* zp = (a == 1) ? z1 : (a == 2) ? z2 : z3;
            uint2 u = *(const uint2*)(zp + (size_t)src * DIM + le);
            if (a == 1) addh4(acc1, u);
            else if (a == 2) addh4(acc2, u);
            else addh4(acc3, u);
        }
    }

    float4 o = make_float4(0.f, 0.f, 0.f, 0.f);
    addh4(o, *(const uint2*)(souts + (size_t)warp * DIM + le));
    {
        float4 b = ((const float4*)(bk_t + 0 * DIM))[lane];
        add4(acc1, b);
        add4(o, relu4(acc1));
    }
    if (kmax >= 2) {
        float4 b = ((const float4*)(bk_t + 1 * DIM))[lane];
        add4(acc2, b);
        add4(o, relu4(acc2));
    }
    if (kmax >= 3) {
        float4 b = ((const float4*)(bk_t + 2 * DIM))[lane];
        add4(acc3, b);
        add4(o, relu4(acc3));
    }
    float4 xv = ((const float4*)xt)[(size_t)warp * 32 + lane];
    float4 h = relu4(o);
    add4(xv, h);
    ((float4*)xnext)[(size_t)warp * 32 + lane] = xv;
}

// ---------------- launch ----------------
extern "C" void kernel_launch(void* const* d_in, const int* in_sizes, int n_in,
                              void* d_out, int out_size) {
    const float* x   = (const float*)d_in[0];
    const int*   ei  = (const int*)d_in[1];   // [2, E]
    const int*   ea  = (const int*)d_in[2];   // [E]
    const float* Ws  = (const float*)d_in[3];
    const float* bs  = (const float*)d_in[4];
    const float* Wk  = (const float*)d_in[5];
    const float* bk  = (const float*)d_in[6];
    const float* eps = (const float*)d_in[7];
    float* out = (float*)d_out;

    int n = in_sizes[0] / DIM;
    int e = in_sizes[2];
    const int* src = ei;
    const int* dst = ei + e;

    float *p_x1, *p_x2;
    __half *p_sout, *p_z0, *p_z1, *p_z2;
    int* p_count;
    cudaGetSymbolAddress((void**)&p_x1, g_x1);
    cudaGetSymbolAddress((void**)&p_x2, g_x2);
    cudaGetSymbolAddress((void**)&p_sout, g_sout);
    cudaGetSymbolAddress((void**)&p_z0, g_z0);
    cudaGetSymbolAddress((void**)&p_z1, g_z1);
    cudaGetSymbolAddress((void**)&p_z2, g_z2);
    cudaGetSymbolAddress((void**)&p_count, g_count);
    __nv_bfloat16 *p_wh, *p_wl;
    cudaGetSymbolAddress((void**)&p_wh, g_whT);
    cudaGetSymbolAddress((void**)&p_wl, g_wlT);

    cudaFuncSetAttribute(mma_gemm2_k, cudaFuncAttributeMaxDynamicSharedMemorySize, SM2_BYTES);

    // ----- weight preprocessing + CSR build -----
    {
        dim3 cgrid(16, 12, 1);
        dim3 cblk(32, 8, 1);
        convw_k<<<cgrid, cblk>>>(Ws, Wk);
    }
    cudaMemsetAsync(p_count, 0, (size_t)n * sizeof(int));
    count_k<<<(e + 255) / 256, 256>>>(dst, e);
    int nb = (n + 1023) / 1024;
    scan1_k<<<nb, 256>>>(n);
    scan2_k<<<1, 64>>>(nb);
    scan3_k<<<(n + 255) / 256, 256>>>(n, e);
    place_k<<<(e + 255) / 256, 256>>>(src, dst, ea, e);

    const float* xs[4];
    xs[0] = x;
    xs[1] = p_x1;
    xs[2] = p_x2;
    xs[3] = out;

    int gemm_grid = (n + 63) / 64;
    int agg_grid = (n * 32 + 255) / 256;
    __half* zbuf[3] = {p_z0, p_z1, p_z2};

    for (int t = 0; t < LAY; t++) {
        // combined launch: sout = (1+eps)*relu(xt@Ws[t]+bs[t])  AND  z0 = xt@Wk[t][0]
        int slot1 = 3 + t * LAY + 0;
        mma_gemm2_k<<<gemm_grid, 128, SM2_BYTES>>>(
            xs[t],
            p_wh + (size_t)t * DIM * DIM, p_wl + (size_t)t * DIM * DIM, p_sout,
            bs + t * DIM, eps + t,
            p_wh + (size_t)slot1 * DIM * DIM, p_wl + (size_t)slot1 * DIM * DIM, zbuf[0],
            n);
        // remaining z_k (k >= 2) each use a different A -> single-product launches
        for (int k = 2; k <= t + 1; k++) {
            int slot = 3 + t * LAY + (k - 1);
            mma_gemm2_k<<<gemm_grid, 128, SM2_BYTES>>>(
                xs[t - (k - 1)],
                p_wh + (size_t)slot * DIM * DIM, p_wl + (size_t)slot * DIM * DIM, zbuf[k - 1],
                nullptr, nullptr,
                nullptr, nullptr, nullptr,
                n);
        }
        aggregate_k<<<agg_grid, 256>>>(xs[t], p_sout, p_z0, p_z1, p_z2,
                                       bk + (size_t)t * LAY * DIM, t + 1,
                                       (float*)xs[t + 1], n);
    }
}